// round 7
// baseline (speedup 1.0000x reference)
#include <cuda_runtime.h>
#include <math.h>

// Problem shapes (fixed by the dataset)
#define BSZ 2048
#define DIM 16
#define FEA 512
#define TPB 256
#define NRB 8              // row blocks: 8 * 256 = 2048 rows
#define NJC 36             // j chunks
#define CHUNK 57           // 36 * 57 = 2052 >= 2048
#define RECON_BLOCKS 256
#define RED_BLOCKS 64      // reduce_rows blocks (warp each, 32 rows/block)

#define LOG2PI 1.8378770664093453f
#define LOG2E  1.4426950408889634f
#define LN2    0.6931471805599453f
#define EINV   0.36787944117144233f   // exp(-1)

// ---------------- scratch (device globals; no allocation) ----------------
// per j: a[16], c1[16], c0[16]   (p_log2 = a*z^2 + c1*z + c0)
__device__ float  g_C[BSZ * 48];
__device__ float  g_lqzx[BSZ];
__device__ float  g_lprior[BSZ];
__device__ float  g_recon[RECON_BLOCKS];
__device__ float  g_part[NJC][17][BSZ];   // per j-chunk partials: 16 per-dim + 1 joint
__device__ double g_rowsum[RED_BLOCKS];

__device__ __forceinline__ float ex2f_(float x) {
    float y;
    asm("ex2.approx.ftz.f32 %0, %1;" : "=f"(y) : "f"(x));
    return y;
}
__device__ __forceinline__ float lg2f_(float x) {
    float y;
    asm("lg2.approx.ftz.f32 %0, %1;" : "=f"(y) : "f"(x));
    return y;
}

// ---------------- prep: per-column constants + row terms ----------------
__global__ void prep_kernel(const float* __restrict__ mu,
                            const float* __restrict__ lv,
                            const float* __restrict__ z) {
    int j = blockIdx.x * blockDim.x + threadIdx.x;
    if (j >= BSZ) return;
    float lqzx = 0.f, lpr = 0.f;
#pragma unroll
    for (int d = 0; d < DIM; ++d) {
        float m  = mu[j * DIM + d];
        float l  = lv[j * DIM + d];
        float zz = z [j * DIM + d];
        float w  = __expf(-l);
        float a  = -0.5f * w * LOG2E;
        float b  = -0.5f * (l + LOG2PI) * LOG2E;
        g_C[j * 48 +      d] = a;
        g_C[j * 48 + 16 + d] = -2.0f * a * m;          // c1
        g_C[j * 48 + 32 + d] = fmaf(a * m, m, b);      // c0 = a*mu^2 + b
        float t = zz - m;
        lqzx += -0.5f * (t * t * w + l + LOG2PI);
        lpr  += -0.5f * (zz * zz * EINV + 1.0f + LOG2PI);
    }
    g_lqzx[j]   = lqzx;
    g_lprior[j] = lpr;
}

// ---------------- recon: mean |x - r| partials ----------------
__global__ void recon_kernel(const float* __restrict__ x,
                             const float* __restrict__ r, int n) {
    __shared__ float sm[TPB / 32];
    float s = 0.f;
    for (int idx = blockIdx.x * blockDim.x + threadIdx.x; idx < n;
         idx += gridDim.x * blockDim.x)
        s += fabsf(x[idx] - r[idx]);
#pragma unroll
    for (int o = 16; o > 0; o >>= 1) s += __shfl_xor_sync(0xffffffffu, s, o);
    int lane = threadIdx.x & 31, wid = threadIdx.x >> 5;
    if (lane == 0) sm[wid] = s;
    __syncthreads();
    if (threadIdx.x == 0) {
        float bs = 0.f;
#pragma unroll
        for (int w = 0; w < TPB / 32; ++w) bs += sm[w];
        g_recon[blockIdx.x] = bs;
    }
}

// ---------------- main pairwise kernel ----------------
__global__ __launch_bounds__(TPB, 2)
void pairwise_kernel(const float* __restrict__ z, const int* __restrict__ nd) {
    __shared__ __align__(16) float sC[CHUNK * 48];

    const int j0 = blockIdx.y * CHUNK;
    const int cn = (BSZ - j0 < CHUNK) ? (BSZ - j0) : CHUNK;

    for (int t = threadIdx.x; t < cn * 48; t += TPB)
        sC[t] = g_C[j0 * 48 + t];

    const int i = blockIdx.x * TPB + threadIdx.x;
    float zr[DIM], z2[DIM];
#pragma unroll
    for (int d = 0; d < DIM; ++d) {
        zr[d] = z[i * DIM + d];
        z2[d] = zr[d] * zr[d];
    }
    __syncthreads();

    const float Nf    = (float)nd[0];
    const float Mf    = (float)(BSZ - 1);
    const float invM  = 1.0f / Mf;
    const float invN  = 1.0f / Nf;
    const float strat = (Nf - Mf) / (Nf * Mf);

    float accD[DIM];
#pragma unroll
    for (int d = 0; d < DIM; ++d) accD[d] = 0.f;
    float accJ = 0.f;

    for (int jj = 0; jj < cn; ++jj) {
        const float4* c4 = (const float4*)(sC + jj * 48);  // uniform -> broadcast
        const int j = j0 + jj;
        float iw = invM;
        if (j == 0)      iw = (i == BSZ - 2) ? strat : invN;
        else if (j == 1) iw = strat;

        float pr0 = iw, pr1 = 1.f, pr2 = 1.f, pr3 = 1.f;
#pragma unroll
        for (int g = 0; g < 4; ++g) {
            float4 A  = c4[g];
            float4 C1 = c4[4 + g];
            float4 C0 = c4[8 + g];
            int d = g * 4;

            float e0 = ex2f_(fmaf(A.x, z2[d+0], fmaf(C1.x, zr[d+0], C0.x)));
            float e1 = ex2f_(fmaf(A.y, z2[d+1], fmaf(C1.y, zr[d+1], C0.y)));
            float e2 = ex2f_(fmaf(A.z, z2[d+2], fmaf(C1.z, zr[d+2], C0.z)));
            float e3 = ex2f_(fmaf(A.w, z2[d+3], fmaf(C1.w, zr[d+3], C0.w)));

            accD[d+0] = fmaf(e0, iw, accD[d+0]);
            accD[d+1] = fmaf(e1, iw, accD[d+1]);
            accD[d+2] = fmaf(e2, iw, accD[d+2]);
            accD[d+3] = fmaf(e3, iw, accD[d+3]);

            pr0 *= e0; pr1 *= e1; pr2 *= e2; pr3 *= e3;
        }
        accJ += (pr0 * pr1) * (pr2 * pr3);
    }

#pragma unroll
    for (int d = 0; d < DIM; ++d) g_part[blockIdx.y][d][i] = accD[d];
    g_part[blockIdx.y][16][i] = accJ;
}

// ---------------- reduce rows: one warp per 32 rows, 64 blocks ----------------
// per-row value: lqzx[i] + 3*log(sum_j joint) - 3*sum_d log(sum_j dim_d) - lprior[i]
__global__ __launch_bounds__(32)
void reduce_rows_kernel() {
    const int i = blockIdx.x * 32 + threadIdx.x;

    float sj = 0.f;
#pragma unroll
    for (int jc = 0; jc < NJC; ++jc) sj += g_part[jc][16][i];
    float lsum = 3.0f * lg2f_(sj);     // accumulate logs in log2; scale by LN2 once

    float lqzp2 = 0.f;
#pragma unroll
    for (int d = 0; d < DIM; ++d) {
        float sd = 0.f;
#pragma unroll
        for (int jc = 0; jc < NJC; ++jc) sd += g_part[jc][d][i];
        lqzp2 += lg2f_(sd);
    }
    lsum -= 3.0f * lqzp2;

    double v = (double)g_lqzx[i] + (double)(lsum * LN2) - (double)g_lprior[i];

    // warp reduce (double via shfl)
#pragma unroll
    for (int o = 16; o > 0; o >>= 1)
        v += __shfl_xor_sync(0xffffffffu, v, o);

    if (threadIdx.x == 0) g_rowsum[blockIdx.x] = v;
}

// ---------------- finalize: tiny deterministic sum ----------------
__global__ void finalize_kernel(float* __restrict__ out) {
    if (threadIdx.x != 0) return;
    double rows = 0.0;
#pragma unroll
    for (int b = 0; b < RED_BLOCKS; ++b) rows += g_rowsum[b];
    double rsum = 0.0;
#pragma unroll
    for (int b = 0; b < RECON_BLOCKS; ++b) rsum += (double)g_recon[b];
    double recon = rsum / (double)(BSZ * FEA);
    out[0] = (float)(recon + rows / (double)BSZ);
}

// ---------------- launch ----------------
extern "C" void kernel_launch(void* const* d_in, const int* in_sizes, int n_in,
                              void* d_out, int out_size) {
    const float* x   = (const float*)d_in[0];
    const float* rec = (const float*)d_in[1];
    const float* mu  = (const float*)d_in[2];
    const float* lv  = (const float*)d_in[3];
    const float* z   = (const float*)d_in[4];
    const int*   nd  = (const int*)  d_in[5];

    prep_kernel<<<(BSZ + TPB - 1) / TPB, TPB>>>(mu, lv, z);
    recon_kernel<<<RECON_BLOCKS, TPB>>>(x, rec, in_sizes[0]);
    dim3 grid(NRB, NJC);
    pairwise_kernel<<<grid, TPB>>>(z, nd);
    reduce_rows_kernel<<<RED_BLOCKS, 32>>>();
    finalize_kernel<<<1, 32>>>((float*)d_out);
}

// round 8
// speedup vs baseline: 1.5952x; 1.5952x over previous
#include <cuda_runtime.h>
#include <math.h>

// Problem shapes (fixed by the dataset)
#define BSZ 2048
#define DIM 16
#define FEA 512
#define TPB 256
#define NRB 8              // row blocks: 8 * 256 = 2048 rows
#define NJC 18             // j chunks
#define CHUNK 114          // ceil(2048/18)
#define RECON_BLOCKS 256

#define LOG2PI 1.8378770664093453f
#define LOG2E  1.4426950408889634f
#define LN2    0.6931471805599453f
#define EINV   0.36787944117144233f   // exp(-1)

// ---------------- scratch (device globals; no allocation) ----------------
__device__ float  g_C[BSZ * 48];           // per j: mu[16], a[16], b[16]
__device__ float  g_lqzx[BSZ];
__device__ float  g_lprior[BSZ];
__device__ float  g_recon[RECON_BLOCKS];
__device__ float  g_part[NJC][17 * BSZ];   // per j-chunk partials: 16 per-dim + 1 joint
__device__ float  g_sum[17 * BSZ];         // jc-compressed partials
__device__ double g_rowsum[NRB];

__device__ __forceinline__ float ex2f_(float x) {
    float y;
    asm("ex2.approx.ftz.f32 %0, %1;" : "=f"(y) : "f"(x));
    return y;
}
__device__ __forceinline__ float lg2f_(float x) {
    float y;
    asm("lg2.approx.ftz.f32 %0, %1;" : "=f"(y) : "f"(x));
    return y;
}

// ---------------- prep: per-column constants + row terms ----------------
__global__ void prep_kernel(const float* __restrict__ mu,
                            const float* __restrict__ lv,
                            const float* __restrict__ z) {
    int j = blockIdx.x * blockDim.x + threadIdx.x;
    if (j >= BSZ) return;
    float lqzx = 0.f, lpr = 0.f;
#pragma unroll
    for (int d = 0; d < DIM; ++d) {
        float m  = mu[j * DIM + d];
        float l  = lv[j * DIM + d];
        float zz = z [j * DIM + d];
        float w  = __expf(-l);
        g_C[j * 48 +      d] = m;
        g_C[j * 48 + 16 + d] = -0.5f * w * LOG2E;
        g_C[j * 48 + 32 + d] = -0.5f * (l + LOG2PI) * LOG2E;
        float t = zz - m;
        lqzx += -0.5f * (t * t * w + l + LOG2PI);
        lpr  += -0.5f * (zz * zz * EINV + 1.0f + LOG2PI);
    }
    g_lqzx[j]   = lqzx;
    g_lprior[j] = lpr;
}

// ---------------- recon: mean |x - r| partials ----------------
__global__ void recon_kernel(const float* __restrict__ x,
                             const float* __restrict__ r, int n) {
    __shared__ float sm[TPB / 32];
    float s = 0.f;
    for (int idx = blockIdx.x * blockDim.x + threadIdx.x; idx < n;
         idx += gridDim.x * blockDim.x)
        s += fabsf(x[idx] - r[idx]);
#pragma unroll
    for (int o = 16; o > 0; o >>= 1) s += __shfl_xor_sync(0xffffffffu, s, o);
    int lane = threadIdx.x & 31, wid = threadIdx.x >> 5;
    if (lane == 0) sm[wid] = s;
    __syncthreads();
    if (threadIdx.x == 0) {
        float bs = 0.f;
#pragma unroll
        for (int w = 0; w < TPB / 32; ++w) bs += sm[w];
        g_recon[blockIdx.x] = bs;
    }
}

// ---------------- main pairwise kernel (proven R6 form) ----------------
__global__ __launch_bounds__(TPB, 1)
void pairwise_kernel(const float* __restrict__ z, const int* __restrict__ nd) {
    __shared__ float sC[CHUNK * 48];

    const int j0 = blockIdx.y * CHUNK;
    const int cn = (BSZ - j0 < CHUNK) ? (BSZ - j0) : CHUNK;

    for (int t = threadIdx.x; t < cn * 48; t += TPB)
        sC[t] = g_C[j0 * 48 + t];

    const int i = blockIdx.x * TPB + threadIdx.x;
    float zr[DIM];
#pragma unroll
    for (int d = 0; d < DIM; ++d) zr[d] = z[i * DIM + d];
    __syncthreads();

    const float Nf    = (float)nd[0];
    const float Mf    = (float)(BSZ - 1);
    const float invM  = 1.0f / Mf;
    const float invN  = 1.0f / Nf;
    const float strat = (Nf - Mf) / (Nf * Mf);

    float accD[DIM];
#pragma unroll
    for (int d = 0; d < DIM; ++d) accD[d] = 0.f;
    float accJ = 0.f;

    for (int jj = 0; jj < cn; ++jj) {
        const float* c = sC + jj * 48;  // uniform across warp -> LDS broadcast
        const int j = j0 + jj;
        float iw = invM;
        if (j == 0)      iw = (i == BSZ - 2) ? strat : invN;
        else if (j == 1) iw = strat;

        float pr0 = iw, pr1 = 1.f, pr2 = 1.f, pr3 = 1.f;
#pragma unroll
        for (int d = 0; d < DIM; ++d) {
            float t = zr[d] - c[d];
            float p = fmaf(t * c[16 + d], t, c[32 + d]);   // (z-mu)^2*a + b, log2 units
            float e = ex2f_(p);
            accD[d] = fmaf(e, iw, accD[d]);
            if      ((d & 3) == 0) pr0 *= e;
            else if ((d & 3) == 1) pr1 *= e;
            else if ((d & 3) == 2) pr2 *= e;
            else                   pr3 *= e;
        }
        accJ += (pr0 * pr1) * (pr2 * pr3);
    }

#pragma unroll
    for (int d = 0; d < DIM; ++d) g_part[blockIdx.y][d * BSZ + i] = accD[d];
    g_part[blockIdx.y][16 * BSZ + i] = accJ;
}

// ---------------- stage A: compress jc axis ----------------
// one thread per (d,i) pair; 18 independent coalesced loads, 1 store
__global__ __launch_bounds__(TPB)
void compress_kernel() {
    const int t = blockIdx.x * TPB + threadIdx.x;   // t < 17 * BSZ
    if (t >= 17 * BSZ) return;
    float s = 0.f;
#pragma unroll
    for (int jc = 0; jc < NJC; ++jc) s += g_part[jc][t];
    g_sum[t] = s;
}

// ---------------- stage B: per-row logs + block reduction ----------------
// per-row value: lqzx[i] + 3*log(joint) - 3*sum_d log(dim_d) - lprior[i]
__global__ __launch_bounds__(TPB)
void rows_kernel() {
    __shared__ double red[TPB];
    const int i = blockIdx.x * TPB + threadIdx.x;

    float lsum = 3.0f * lg2f_(g_sum[16 * BSZ + i]);
    float lqzp2 = 0.f;
#pragma unroll
    for (int d = 0; d < DIM; ++d)
        lqzp2 += lg2f_(g_sum[d * BSZ + i]);
    lsum -= 3.0f * lqzp2;

    double v = (double)g_lqzx[i] + (double)(lsum * LN2) - (double)g_lprior[i];

    red[threadIdx.x] = v;
    __syncthreads();
#pragma unroll
    for (int s = TPB / 2; s > 0; s >>= 1) {
        if (threadIdx.x < s) red[threadIdx.x] += red[threadIdx.x + s];
        __syncthreads();
    }
    if (threadIdx.x == 0) g_rowsum[blockIdx.x] = red[0];
}

// ---------------- finalize: tiny deterministic sum ----------------
__global__ void finalize_kernel(float* __restrict__ out) {
    if (threadIdx.x != 0) return;
    double rows = 0.0;
#pragma unroll
    for (int b = 0; b < NRB; ++b) rows += g_rowsum[b];
    double rsum = 0.0;
#pragma unroll
    for (int b = 0; b < RECON_BLOCKS; ++b) rsum += (double)g_recon[b];
    double recon = rsum / (double)(BSZ * FEA);
    out[0] = (float)(recon + rows / (double)BSZ);
}

// ---------------- launch ----------------
extern "C" void kernel_launch(void* const* d_in, const int* in_sizes, int n_in,
                              void* d_out, int out_size) {
    const float* x   = (const float*)d_in[0];
    const float* rec = (const float*)d_in[1];
    const float* mu  = (const float*)d_in[2];
    const float* lv  = (const float*)d_in[3];
    const float* z   = (const float*)d_in[4];
    const int*   nd  = (const int*)  d_in[5];

    prep_kernel<<<(BSZ + TPB - 1) / TPB, TPB>>>(mu, lv, z);
    recon_kernel<<<RECON_BLOCKS, TPB>>>(x, rec, in_sizes[0]);
    dim3 grid(NRB, NJC);
    pairwise_kernel<<<grid, TPB>>>(z, nd);
    compress_kernel<<<(17 * BSZ + TPB - 1) / TPB, TPB>>>();
    rows_kernel<<<NRB, TPB>>>();
    finalize_kernel<<<1, 32>>>((float*)d_out);
}

// round 13
// speedup vs baseline: 1.7262x; 1.0821x over previous
#include <cuda_runtime.h>
#include <math.h>

// Problem shapes (fixed by the dataset)
#define BSZ 2048
#define DIM 16
#define FEA 512
#define TPB 256
#define NRB 8              // row blocks: 8 * 256 = 2048 rows
#define NJC 18             // j chunks
#define CHUNK 114          // ceil(2048/18)
#define RECON_BLOCKS 256

#define LOG2PI 1.8378770664093453f
#define LOG2E  1.4426950408889634f
#define LN2    0.6931471805599453f
#define EINV   0.36787944117144233f   // exp(-1)

// ---------------- scratch (device globals; no allocation) ----------------
// per j: A[16], C1[16], C0[16]   (p_log2 = A*z^2 + C1*z + C0)
__device__ __align__(16) float g_C[BSZ * 48];
__device__ float  g_lqzx[BSZ];
__device__ float  g_lprior[BSZ];
__device__ float  g_recon[RECON_BLOCKS];
__device__ float  g_part[NJC][17 * BSZ];   // per j-chunk partials: 16 per-dim + 1 joint
__device__ float  g_sum[17 * BSZ];         // jc-compressed partials
__device__ double g_rowsum[NRB];

__device__ __forceinline__ float ex2f_(float x) {
    float y;
    asm("ex2.approx.ftz.f32 %0, %1;" : "=f"(y) : "f"(x));
    return y;
}
__device__ __forceinline__ float lg2f_(float x) {
    float y;
    asm("lg2.approx.ftz.f32 %0, %1;" : "=f"(y) : "f"(x));
    return y;
}

// ---------------- prep: per-column constants + row terms ----------------
__global__ void prep_kernel(const float* __restrict__ mu,
                            const float* __restrict__ lv,
                            const float* __restrict__ z) {
    int j = blockIdx.x * blockDim.x + threadIdx.x;
    if (j >= BSZ) return;
    float lqzx = 0.f, lpr = 0.f;
#pragma unroll
    for (int d = 0; d < DIM; ++d) {
        float m  = mu[j * DIM + d];
        float l  = lv[j * DIM + d];
        float zz = z [j * DIM + d];
        float w  = __expf(-l);
        float a  = -0.5f * w * LOG2E;
        float b  = -0.5f * (l + LOG2PI) * LOG2E;
        g_C[j * 48 +      d] = a;                     // A
        g_C[j * 48 + 16 + d] = -2.0f * a * m;         // C1
        g_C[j * 48 + 32 + d] = fmaf(a * m, m, b);     // C0 = a*mu^2 + b
        float t = zz - m;
        lqzx += -0.5f * (t * t * w + l + LOG2PI);
        lpr  += -0.5f * (zz * zz * EINV + 1.0f + LOG2PI);
    }
    g_lqzx[j]   = lqzx;
    g_lprior[j] = lpr;
}

// ---------------- recon: mean |x - r| partials ----------------
__global__ void recon_kernel(const float* __restrict__ x,
                             const float* __restrict__ r, int n) {
    __shared__ float sm[TPB / 32];
    float s = 0.f;
    for (int idx = blockIdx.x * blockDim.x + threadIdx.x; idx < n;
         idx += gridDim.x * blockDim.x)
        s += fabsf(x[idx] - r[idx]);
#pragma unroll
    for (int o = 16; o > 0; o >>= 1) s += __shfl_xor_sync(0xffffffffu, s, o);
    int lane = threadIdx.x & 31, wid = threadIdx.x >> 5;
    if (lane == 0) sm[wid] = s;
    __syncthreads();
    if (threadIdx.x == 0) {
        float bs = 0.f;
#pragma unroll
        for (int w = 0; w < TPB / 32; ++w) bs += sm[w];
        g_recon[blockIdx.x] = bs;
    }
}

// ---------------- pairwise inner body ----------------
// W=true: per-j importance weight folded into accD fma + pr0.
// W=false: unweighted accumulate (scale once at loop exit).
template <bool W>
__device__ __forceinline__ void pair_body(const float4* __restrict__ c4,
                                          const float zr[DIM], const float z2[DIM],
                                          float iw, float accD[DIM], float& accJ) {
    float pr0 = W ? iw : 1.f, pr1 = 1.f, pr2 = 1.f, pr3 = 1.f;
#pragma unroll
    for (int g = 0; g < 4; ++g) {
        float4 A  = c4[g];
        float4 C1 = c4[4 + g];
        float4 C0 = c4[8 + g];
        const int d = g * 4;

        float e0 = ex2f_(fmaf(A.x, z2[d+0], fmaf(C1.x, zr[d+0], C0.x)));
        float e1 = ex2f_(fmaf(A.y, z2[d+1], fmaf(C1.y, zr[d+1], C0.y)));
        float e2 = ex2f_(fmaf(A.z, z2[d+2], fmaf(C1.z, zr[d+2], C0.z)));
        float e3 = ex2f_(fmaf(A.w, z2[d+3], fmaf(C1.w, zr[d+3], C0.w)));

        if (W) {
            accD[d+0] = fmaf(e0, iw, accD[d+0]);
            accD[d+1] = fmaf(e1, iw, accD[d+1]);
            accD[d+2] = fmaf(e2, iw, accD[d+2]);
            accD[d+3] = fmaf(e3, iw, accD[d+3]);
        } else {
            accD[d+0] += e0;
            accD[d+1] += e1;
            accD[d+2] += e2;
            accD[d+3] += e3;
        }
        pr0 *= e0; pr1 *= e1; pr2 *= e2; pr3 *= e3;
    }
    accJ = fmaf(pr0 * pr1, pr2 * pr3, accJ);
}

// ---------------- main pairwise kernel ----------------
__global__ __launch_bounds__(TPB, 1)
void pairwise_kernel(const float* __restrict__ z, const int* __restrict__ nd) {
    __shared__ __align__(16) float sC[CHUNK * 48];

    const int j0 = blockIdx.y * CHUNK;
    const int cn = (BSZ - j0 < CHUNK) ? (BSZ - j0) : CHUNK;

    for (int t = threadIdx.x; t < cn * 48; t += TPB)
        sC[t] = g_C[j0 * 48 + t];

    const int i = blockIdx.x * TPB + threadIdx.x;
    float zr[DIM], z2[DIM];
#pragma unroll
    for (int d = 0; d < DIM; ++d) {
        zr[d] = z[i * DIM + d];
        z2[d] = zr[d] * zr[d];
    }
    __syncthreads();

    const float Nf    = (float)nd[0];
    const float Mf    = (float)(BSZ - 1);
    const float invM  = 1.0f / Mf;
    const float invN  = 1.0f / Nf;
    const float strat = (Nf - Mf) / (Nf * Mf);

    float accD[DIM];
#pragma unroll
    for (int d = 0; d < DIM; ++d) accD[d] = 0.f;
    float accJ = 0.f;

    if (j0 == 0) {
        // general chunk: j=0 and j=1 carry special weights
        float iw0 = (i == BSZ - 2) ? strat : invN;
        pair_body<true>((const float4*)(sC + 0 * 48), zr, z2, iw0,   accD, accJ);
        pair_body<true>((const float4*)(sC + 1 * 48), zr, z2, strat, accD, accJ);
        for (int jj = 2; jj < cn; ++jj)
            pair_body<true>((const float4*)(sC + jj * 48), zr, z2, invM, accD, accJ);
    } else {
        // uniform chunk: all weights invM -> fold once at the end
        for (int jj = 0; jj < cn; ++jj)
            pair_body<false>((const float4*)(sC + jj * 48), zr, z2, 0.f, accD, accJ);
#pragma unroll
        for (int d = 0; d < DIM; ++d) accD[d] *= invM;
        accJ *= invM;
    }

#pragma unroll
    for (int d = 0; d < DIM; ++d) g_part[blockIdx.y][d * BSZ + i] = accD[d];
    g_part[blockIdx.y][16 * BSZ + i] = accJ;
}

// ---------------- stage A: compress jc axis ----------------
__global__ __launch_bounds__(TPB)
void compress_kernel() {
    const int t = blockIdx.x * TPB + threadIdx.x;   // t < 17 * BSZ
    if (t >= 17 * BSZ) return;
    float s = 0.f;
#pragma unroll
    for (int jc = 0; jc < NJC; ++jc) s += g_part[jc][t];
    g_sum[t] = s;
}

// ---------------- stage B: per-row logs + block reduction ----------------
__global__ __launch_bounds__(TPB)
void rows_kernel() {
    __shared__ double red[TPB];
    const int i = blockIdx.x * TPB + threadIdx.x;

    float lsum = 3.0f * lg2f_(g_sum[16 * BSZ + i]);
    float lqzp2 = 0.f;
#pragma unroll
    for (int d = 0; d < DIM; ++d)
        lqzp2 += lg2f_(g_sum[d * BSZ + i]);
    lsum -= 3.0f * lqzp2;

    double v = (double)g_lqzx[i] + (double)(lsum * LN2) - (double)g_lprior[i];

    red[threadIdx.x] = v;
    __syncthreads();
#pragma unroll
    for (int s = TPB / 2; s > 0; s >>= 1) {
        if (threadIdx.x < s) red[threadIdx.x] += red[threadIdx.x + s];
        __syncthreads();
    }
    if (threadIdx.x == 0) g_rowsum[blockIdx.x] = red[0];
}

// ---------------- finalize: tiny deterministic sum ----------------
__global__ void finalize_kernel(float* __restrict__ out) {
    if (threadIdx.x != 0) return;
    double rows = 0.0;
#pragma unroll
    for (int b = 0; b < NRB; ++b) rows += g_rowsum[b];
    double rsum = 0.0;
#pragma unroll
    for (int b = 0; b < RECON_BLOCKS; ++b) rsum += (double)g_recon[b];
    double recon = rsum / (double)(BSZ * FEA);
    out[0] = (float)(recon + rows / (double)BSZ);
}

// ---------------- launch ----------------
extern "C" void kernel_launch(void* const* d_in, const int* in_sizes, int n_in,
                              void* d_out, int out_size) {
    const float* x   = (const float*)d_in[0];
    const float* rec = (const float*)d_in[1];
    const float* mu  = (const float*)d_in[2];
    const float* lv  = (const float*)d_in[3];
    const float* z   = (const float*)d_in[4];
    const int*   nd  = (const int*)  d_in[5];

    prep_kernel<<<(BSZ + TPB - 1) / TPB, TPB>>>(mu, lv, z);
    recon_kernel<<<RECON_BLOCKS, TPB>>>(x, rec, in_sizes[0]);
    dim3 grid(NRB, NJC);
    pairwise_kernel<<<grid, TPB>>>(z, nd);
    compress_kernel<<<(17 * BSZ + TPB - 1) / TPB, TPB>>>();
    rows_kernel<<<NRB, TPB>>>();
    finalize_kernel<<<1, 32>>>((float*)d_out);
}

// round 14
// speedup vs baseline: 1.7309x; 1.0027x over previous
#include <cuda_runtime.h>
#include <math.h>

// Problem shapes (fixed by the dataset)
#define BSZ 2048
#define DIM 16
#define FEA 512
#define TPB 256
#define NRB 8              // row blocks: 8 * 256 = 2048 rows
#define NJC 37             // j chunks  (8*37 = 296 blocks = 2/SM on 148 SMs)
#define CHUNK 56           // 37 * 56 = 2072 >= 2048
#define RECON_BLOCKS 256

#define LOG2PI 1.8378770664093453f
#define LOG2E  1.4426950408889634f
#define LN2    0.6931471805599453f
#define EINV   0.36787944117144233f   // exp(-1)

// ---------------- scratch (device globals; no allocation) ----------------
// per j: A[16], C1[16], C0[16]   (p_log2 = A*z^2 + C1*z + C0)
__device__ __align__(16) float g_C[BSZ * 48];
__device__ float  g_lqzx[BSZ];
__device__ float  g_lprior[BSZ];
__device__ float  g_recon[RECON_BLOCKS];
__device__ float  g_part[NJC][17 * BSZ];   // per j-chunk partials: 16 per-dim + 1 joint
__device__ float  g_sum[17 * BSZ];         // jc-compressed partials
__device__ double g_rowsum[NRB];

__device__ __forceinline__ float ex2f_(float x) {
    float y;
    asm("ex2.approx.ftz.f32 %0, %1;" : "=f"(y) : "f"(x));
    return y;
}
__device__ __forceinline__ float lg2f_(float x) {
    float y;
    asm("lg2.approx.ftz.f32 %0, %1;" : "=f"(y) : "f"(x));
    return y;
}

// ---------------- prep: per-column constants + row terms ----------------
__global__ void prep_kernel(const float* __restrict__ mu,
                            const float* __restrict__ lv,
                            const float* __restrict__ z) {
    int j = blockIdx.x * blockDim.x + threadIdx.x;
    if (j >= BSZ) return;
    float lqzx = 0.f, lpr = 0.f;
#pragma unroll
    for (int d = 0; d < DIM; ++d) {
        float m  = mu[j * DIM + d];
        float l  = lv[j * DIM + d];
        float zz = z [j * DIM + d];
        float w  = __expf(-l);
        float a  = -0.5f * w * LOG2E;
        float b  = -0.5f * (l + LOG2PI) * LOG2E;
        g_C[j * 48 +      d] = a;                     // A
        g_C[j * 48 + 16 + d] = -2.0f * a * m;         // C1
        g_C[j * 48 + 32 + d] = fmaf(a * m, m, b);     // C0 = a*mu^2 + b
        float t = zz - m;
        lqzx += -0.5f * (t * t * w + l + LOG2PI);
        lpr  += -0.5f * (zz * zz * EINV + 1.0f + LOG2PI);
    }
    g_lqzx[j]   = lqzx;
    g_lprior[j] = lpr;
}

// ---------------- recon: mean |x - r| partials ----------------
__global__ void recon_kernel(const float* __restrict__ x,
                             const float* __restrict__ r, int n) {
    __shared__ float sm[TPB / 32];
    float s = 0.f;
    for (int idx = blockIdx.x * blockDim.x + threadIdx.x; idx < n;
         idx += gridDim.x * blockDim.x)
        s += fabsf(x[idx] - r[idx]);
#pragma unroll
    for (int o = 16; o > 0; o >>= 1) s += __shfl_xor_sync(0xffffffffu, s, o);
    int lane = threadIdx.x & 31, wid = threadIdx.x >> 5;
    if (lane == 0) sm[wid] = s;
    __syncthreads();
    if (threadIdx.x == 0) {
        float bs = 0.f;
#pragma unroll
        for (int w = 0; w < TPB / 32; ++w) bs += sm[w];
        g_recon[blockIdx.x] = bs;
    }
}

// ---------------- pairwise inner body ----------------
// W=true: per-j importance weight folded into accD fma + pr0.
// W=false: unweighted accumulate (scale once at loop exit).
template <bool W>
__device__ __forceinline__ void pair_body(const float4* __restrict__ c4,
                                          const float zr[DIM], const float z2[DIM],
                                          float iw, float accD[DIM], float& accJ) {
    float pr0 = W ? iw : 1.f, pr1 = 1.f, pr2 = 1.f, pr3 = 1.f;
#pragma unroll
    for (int g = 0; g < 4; ++g) {
        float4 A  = c4[g];
        float4 C1 = c4[4 + g];
        float4 C0 = c4[8 + g];
        const int d = g * 4;

        float e0 = ex2f_(fmaf(A.x, z2[d+0], fmaf(C1.x, zr[d+0], C0.x)));
        float e1 = ex2f_(fmaf(A.y, z2[d+1], fmaf(C1.y, zr[d+1], C0.y)));
        float e2 = ex2f_(fmaf(A.z, z2[d+2], fmaf(C1.z, zr[d+2], C0.z)));
        float e3 = ex2f_(fmaf(A.w, z2[d+3], fmaf(C1.w, zr[d+3], C0.w)));

        if (W) {
            accD[d+0] = fmaf(e0, iw, accD[d+0]);
            accD[d+1] = fmaf(e1, iw, accD[d+1]);
            accD[d+2] = fmaf(e2, iw, accD[d+2]);
            accD[d+3] = fmaf(e3, iw, accD[d+3]);
        } else {
            accD[d+0] += e0;
            accD[d+1] += e1;
            accD[d+2] += e2;
            accD[d+3] += e3;
        }
        pr0 *= e0; pr1 *= e1; pr2 *= e2; pr3 *= e3;
    }
    accJ = fmaf(pr0 * pr1, pr2 * pr3, accJ);
}

// ---------------- main pairwise kernel ----------------
__global__ __launch_bounds__(TPB)
void pairwise_kernel(const float* __restrict__ z, const int* __restrict__ nd) {
    __shared__ __align__(16) float sC[CHUNK * 48];

    const int j0 = blockIdx.y * CHUNK;
    const int cn = (BSZ - j0 < CHUNK) ? (BSZ - j0) : CHUNK;

    for (int t = threadIdx.x; t < cn * 48; t += TPB)
        sC[t] = g_C[j0 * 48 + t];

    const int i = blockIdx.x * TPB + threadIdx.x;
    float zr[DIM], z2[DIM];
#pragma unroll
    for (int d = 0; d < DIM; ++d) {
        zr[d] = z[i * DIM + d];
        z2[d] = zr[d] * zr[d];
    }
    __syncthreads();

    const float Nf    = (float)nd[0];
    const float Mf    = (float)(BSZ - 1);
    const float invM  = 1.0f / Mf;
    const float invN  = 1.0f / Nf;
    const float strat = (Nf - Mf) / (Nf * Mf);

    float accD[DIM];
#pragma unroll
    for (int d = 0; d < DIM; ++d) accD[d] = 0.f;
    float accJ = 0.f;

    if (j0 == 0) {
        // general chunk: j=0 and j=1 carry special weights
        float iw0 = (i == BSZ - 2) ? strat : invN;
        pair_body<true>((const float4*)(sC + 0 * 48), zr, z2, iw0,   accD, accJ);
        pair_body<true>((const float4*)(sC + 1 * 48), zr, z2, strat, accD, accJ);
#pragma unroll 2
        for (int jj = 2; jj < cn; ++jj)
            pair_body<true>((const float4*)(sC + jj * 48), zr, z2, invM, accD, accJ);
    } else {
        // uniform chunk: all weights invM -> fold once at the end
#pragma unroll 2
        for (int jj = 0; jj < cn; ++jj)
            pair_body<false>((const float4*)(sC + jj * 48), zr, z2, 0.f, accD, accJ);
#pragma unroll
        for (int d = 0; d < DIM; ++d) accD[d] *= invM;
        accJ *= invM;
    }

#pragma unroll
    for (int d = 0; d < DIM; ++d) g_part[blockIdx.y][d * BSZ + i] = accD[d];
    g_part[blockIdx.y][16 * BSZ + i] = accJ;
}

// ---------------- stage A: compress jc axis ----------------
__global__ __launch_bounds__(TPB)
void compress_kernel() {
    const int t = blockIdx.x * TPB + threadIdx.x;   // t < 17 * BSZ
    if (t >= 17 * BSZ) return;
    float s = 0.f;
#pragma unroll
    for (int jc = 0; jc < NJC; ++jc) s += g_part[jc][t];
    g_sum[t] = s;
}

// ---------------- stage B: per-row logs + block reduction ----------------
__global__ __launch_bounds__(TPB)
void rows_kernel() {
    __shared__ double red[TPB];
    const int i = blockIdx.x * TPB + threadIdx.x;

    float lsum = 3.0f * lg2f_(g_sum[16 * BSZ + i]);
    float lqzp2 = 0.f;
#pragma unroll
    for (int d = 0; d < DIM; ++d)
        lqzp2 += lg2f_(g_sum[d * BSZ + i]);
    lsum -= 3.0f * lqzp2;

    double v = (double)g_lqzx[i] + (double)(lsum * LN2) - (double)g_lprior[i];

    red[threadIdx.x] = v;
    __syncthreads();
#pragma unroll
    for (int s = TPB / 2; s > 0; s >>= 1) {
        if (threadIdx.x < s) red[threadIdx.x] += red[threadIdx.x + s];
        __syncthreads();
    }
    if (threadIdx.x == 0) g_rowsum[blockIdx.x] = red[0];
}

// ---------------- finalize: tiny deterministic sum ----------------
__global__ void finalize_kernel(float* __restrict__ out) {
    if (threadIdx.x != 0) return;
    double rows = 0.0;
#pragma unroll
    for (int b = 0; b < NRB; ++b) rows += g_rowsum[b];
    double rsum = 0.0;
#pragma unroll
    for (int b = 0; b < RECON_BLOCKS; ++b) rsum += (double)g_recon[b];
    double recon = rsum / (double)(BSZ * FEA);
    out[0] = (float)(recon + rows / (double)BSZ);
}

// ---------------- launch ----------------
extern "C" void kernel_launch(void* const* d_in, const int* in_sizes, int n_in,
                              void* d_out, int out_size) {
    const float* x   = (const float*)d_in[0];
    const float* rec = (const float*)d_in[1];
    const float* mu  = (const float*)d_in[2];
    const float* lv  = (const float*)d_in[3];
    const float* z   = (const float*)d_in[4];
    const int*   nd  = (const int*)  d_in[5];

    prep_kernel<<<(BSZ + TPB - 1) / TPB, TPB>>>(mu, lv, z);
    recon_kernel<<<RECON_BLOCKS, TPB>>>(x, rec, in_sizes[0]);
    dim3 grid(NRB, NJC);
    pairwise_kernel<<<grid, TPB>>>(z, nd);
    compress_kernel<<<(17 * BSZ + TPB - 1) / TPB, TPB>>>();
    rows_kernel<<<NRB, TPB>>>();
    finalize_kernel<<<1, 32>>>((float*)d_out);
}